// round 6
// baseline (speedup 1.0000x reference)
#include <cuda_runtime.h>
#include <cuda_bf16.h>
#include <cstdint>

// Problem constants
#define NN   100000
#define RR   3
#define EE   320000
#define HIDD 128
#define HH   4
#define DD   32
#define HDIM 128   // HH*DD

// ---------------------------------------------------------------------------
// Scratch (device globals; no runtime allocation)
// ---------------------------------------------------------------------------
__device__ __align__(16) float  g_Wc [RR * 128 * 128];   // folded src weight: Wt_src@Wg
__device__ __align__(16) float  g_bc [RR * 128];         // folded src bias:  bt_src@Wg
__device__ __align__(16) float  g_Vt [RR * HH * 128];    // [r][h][f]  dst-side folded vector
__device__ __align__(16) float  g_cc [RR * HH];          // dst-side folded bias
__device__ __align__(16) float  g_hs [(size_t)RR * NN * 128];  // 153.6 MB
__device__ __align__(16) float  g_rst[(size_t)RR * NN * 128];  // 153.6 MB (becomes z after elu)
__device__ float4 g_el  [RR * NN];   // per-node left attention logits (4 heads)
__device__ float4 g_er  [RR * NN];   // per-node right attention logits
__device__ float4 g_ex  [RR * EE];   // per-edge exp(leaky(e))
__device__ float4 g_ssum[RR * NN];   // per-dst softmax denominators
__device__ float  g_wsum[RR];
__device__ float  g_a   [RR];

// ---------------------------------------------------------------------------
// Helpers
// ---------------------------------------------------------------------------
__device__ __forceinline__ void red_add_v4(float4* p, float4 v) {
    asm volatile("red.global.add.v4.f32 [%0], {%1,%2,%3,%4};"
                 :: "l"(p), "f"(v.x), "f"(v.y), "f"(v.z), "f"(v.w) : "memory");
}

// ---------------------------------------------------------------------------
// Kernel 0: zero accumulators
// ---------------------------------------------------------------------------
__global__ void init_kernel() {
    size_t stride = (size_t)gridDim.x * blockDim.x;
    size_t i = (size_t)blockIdx.x * blockDim.x + threadIdx.x;
    float4 z = make_float4(0.f, 0.f, 0.f, 0.f);
    float4* r4 = (float4*)g_rst;
    size_t n4 = (size_t)RR * NN * 32;
    for (size_t j = i; j < n4; j += stride) r4[j] = z;
    for (size_t j = i; j < (size_t)RR * NN; j += stride) g_ssum[j] = z;
    if (i < RR) g_wsum[i] = 0.f;
}

// ---------------------------------------------------------------------------
// Kernel 1: folded source weight  Wc[r] = Wt_src[r] @ Wg[r],  bc[r] = bt_src[r] @ Wg[r]
// ---------------------------------------------------------------------------
__global__ __launch_bounds__(256) void prep_wc_kernel(
        const float* __restrict__ Wt_src, const float* __restrict__ Wg,
        const float* __restrict__ bt_src) {
    int r = blockIdx.x;
    const float* Wt  = Wt_src + r * 128 * 128;
    const float* Wgr = Wg     + r * 128 * 128;
    __shared__ float Wgs[32][128];
    int tid = threadIdx.x;
    int lane = tid & 31;
    int f0 = (tid >> 5) * 16;
    float acc[16][4] = {};
    for (int kk = 0; kk < 128; kk += 32) {
        for (int idx = tid; idx < 32 * 128; idx += 256)
            Wgs[idx >> 7][idx & 127] = Wgr[(kk + (idx >> 7)) * 128 + (idx & 127)];
        __syncthreads();
        for (int k = 0; k < 32; k++) {
            float4 w = *(const float4*)&Wgs[k][lane * 4];
            #pragma unroll
            for (int i = 0; i < 16; i++) {
                float x = __ldg(&Wt[(f0 + i) * 128 + kk + k]);
                acc[i][0] += x * w.x; acc[i][1] += x * w.y;
                acc[i][2] += x * w.z; acc[i][3] += x * w.w;
            }
        }
        __syncthreads();
    }
    #pragma unroll
    for (int i = 0; i < 16; i++)
        *(float4*)&g_Wc[(r * 128 + f0 + i) * 128 + lane * 4] =
            make_float4(acc[i][0], acc[i][1], acc[i][2], acc[i][3]);
    if (tid < 128) {
        float s = 0.f;
        for (int k = 0; k < 128; k++) s += bt_src[r * 128 + k] * Wgr[k * 128 + tid];
        g_bc[r * 128 + tid] = s;
    }
}

// ---------------------------------------------------------------------------
// Kernel 2: dst-side fold. P[k][h] = sum_d Wg[r][k][h*32+d]*attn_r[r][h][d]
//           Vt[r][h][f] = sum_k Wt_dst[f][k]*P[k][h];  cc[r][h] = sum_k bt_dst[k]*P[k][h]
// ---------------------------------------------------------------------------
__global__ void prep_v_kernel(const float* __restrict__ Wt_dst,
                              const float* __restrict__ bt_dst,
                              const float* __restrict__ Wg,
                              const float* __restrict__ attn_r) {
    int r = blockIdx.x;
    __shared__ float P[128][4];
    int tid = threadIdx.x;   // 128 threads
    const float* Wgr = Wg + r * 128 * 128;
    #pragma unroll
    for (int h = 0; h < 4; h++) {
        float s = 0.f;
        for (int d = 0; d < 32; d++)
            s += Wgr[tid * 128 + h * 32 + d] * attn_r[(r * 4 + h) * 32 + d];
        P[tid][h] = s;
    }
    __syncthreads();
    float v0 = 0.f, v1 = 0.f, v2 = 0.f, v3 = 0.f;
    for (int k = 0; k < 128; k++) {
        float wt = Wt_dst[tid * 128 + k];
        v0 += wt * P[k][0]; v1 += wt * P[k][1];
        v2 += wt * P[k][2]; v3 += wt * P[k][3];
    }
    g_Vt[(r * 4 + 0) * 128 + tid] = v0;
    g_Vt[(r * 4 + 1) * 128 + tid] = v1;
    g_Vt[(r * 4 + 2) * 128 + tid] = v2;
    g_Vt[(r * 4 + 3) * 128 + tid] = v3;
    if (tid < 4) {
        float s = 0.f;
        for (int k = 0; k < 128; k++) s += bt_dst[k] * P[k][tid];
        g_cc[r * 4 + tid] = s;
    }
}

// ---------------------------------------------------------------------------
// Kernel 3: hs[r] = src_feats[r] @ Wc[r] + bc[r]   (and el epilogue)
// Tile: 64 rows x 128 cols per block, 256 threads, K chunked by 32.
// ---------------------------------------------------------------------------
__global__ __launch_bounds__(256) void hs_gemm_kernel(
        const float* __restrict__ src_feats, const float* __restrict__ attn_l) {
    int r = blockIdx.y;
    int row0 = blockIdx.x * 64;
    __shared__ float Ws[32][128];
    __shared__ float Xs[64][32];
    int tid = threadIdx.x;
    int lane = tid & 31;
    int wg = tid >> 5;
    const float* X = src_feats + (size_t)r * NN * 128;
    const float* W = g_Wc + r * 128 * 128;
    float acc[8][4] = {};
    for (int kk = 0; kk < 128; kk += 32) {
        for (int idx = tid; idx < 64 * 32; idx += 256) {
            int i = idx >> 5, k = idx & 31;
            int row = row0 + i;
            Xs[i][k] = (row < NN) ? X[(size_t)row * 128 + kk + k] : 0.f;
        }
        for (int idx = tid; idx < 32 * 128; idx += 256) {
            int k = idx >> 7, g = idx & 127;
            Ws[k][g] = W[(kk + k) * 128 + g];
        }
        __syncthreads();
        #pragma unroll
        for (int k = 0; k < 32; k++) {
            float4 w = *(const float4*)&Ws[k][lane * 4];
            #pragma unroll
            for (int i = 0; i < 8; i++) {
                float x = Xs[wg * 8 + i][k];
                acc[i][0] += x * w.x; acc[i][1] += x * w.y;
                acc[i][2] += x * w.z; acc[i][3] += x * w.w;
            }
        }
        __syncthreads();
    }
    float4 bc = *(const float4*)&g_bc[r * 128 + lane * 4];
    int h = lane >> 3;
    float4 alv = *(const float4*)&attn_l[(r * 4 + h) * 32 + (lane & 7) * 4];
    #pragma unroll
    for (int i = 0; i < 8; i++) {
        int row = row0 + wg * 8 + i;
        float a0 = acc[i][0] + bc.x, a1 = acc[i][1] + bc.y;
        float a2 = acc[i][2] + bc.z, a3 = acc[i][3] + bc.w;
        float p = a0 * alv.x + a1 * alv.y + a2 * alv.z + a3 * alv.w;
        p += __shfl_xor_sync(0xffffffffu, p, 4, 8);
        p += __shfl_xor_sync(0xffffffffu, p, 2, 8);
        p += __shfl_xor_sync(0xffffffffu, p, 1, 8);
        if (row < NN) {
            *(float4*)&g_hs[((size_t)r * NN + row) * 128 + lane * 4] =
                make_float4(a0, a1, a2, a3);
            if ((lane & 7) == 0)
                ((float*)g_el)[((size_t)r * NN + row) * 4 + h] = p;
        }
    }
}

// ---------------------------------------------------------------------------
// Kernel 4: er[r][n][h] = dst_feat[n] . Vt[r][h] + cc[r][h]   (warp per node)
// ---------------------------------------------------------------------------
__global__ __launch_bounds__(256) void er_kernel(const float* __restrict__ dst_feat) {
    int node = (int)((blockIdx.x * (size_t)blockDim.x + threadIdx.x) >> 5);
    int lane = threadIdx.x & 31;
    if (node >= NN) return;
    float4 xv = *(const float4*)&dst_feat[(size_t)node * 128 + lane * 4];
    float p[12];
    #pragma unroll
    for (int rh = 0; rh < 12; rh++) {
        float4 v = *(const float4*)&g_Vt[rh * 128 + lane * 4];
        p[rh] = xv.x * v.x + xv.y * v.y + xv.z * v.z + xv.w * v.w;
    }
    #pragma unroll
    for (int rh = 0; rh < 12; rh++) {
        #pragma unroll
        for (int off = 16; off; off >>= 1)
            p[rh] += __shfl_xor_sync(0xffffffffu, p[rh], off);
    }
    if (lane == 0) {
        #pragma unroll
        for (int r = 0; r < RR; r++)
            g_er[r * NN + node] = make_float4(
                p[r * 4 + 0] + g_cc[r * 4 + 0], p[r * 4 + 1] + g_cc[r * 4 + 1],
                p[r * 4 + 2] + g_cc[r * 4 + 2], p[r * 4 + 3] + g_cc[r * 4 + 3]);
    }
}

// ---------------------------------------------------------------------------
// Kernel 5: per edge: ex = exp(leaky(el[s]+er[d])); ssum[d] += ex
// (segment-max dropped: alpha ratio is shift-invariant; |e| ~ O(1) so exp is safe)
// ---------------------------------------------------------------------------
__global__ __launch_bounds__(256) void edge_pass1(const int* __restrict__ sidx,
                                                  const int* __restrict__ didx) {
    int r = blockIdx.y;
    int e = blockIdx.x * blockDim.x + threadIdx.x;
    if (e >= EE) return;
    int s = __ldg(&sidx[r * EE + e]);
    int d = __ldg(&didx[r * EE + e]);
    float4 el = g_el[r * NN + s];
    float4 er = g_er[r * NN + d];
    float4 ex;
    { float v = el.x + er.x; v = v > 0.f ? v : 0.2f * v; ex.x = expf(v); }
    { float v = el.y + er.y; v = v > 0.f ? v : 0.2f * v; ex.y = expf(v); }
    { float v = el.z + er.z; v = v > 0.f ? v : 0.2f * v; ex.z = expf(v); }
    { float v = el.w + er.w; v = v > 0.f ? v : 0.2f * v; ex.w = expf(v); }
    g_ex[r * EE + e] = ex;
    red_add_v4(&g_ssum[r * NN + d], ex);
}

// ---------------------------------------------------------------------------
// Kernel 6: per edge: alpha = ex/(ssum[d]+1e-9); rst[d] += alpha * hs[s]
// One warp per edge; vectorized red.v4 scatter (hs & rst per relation fit L2).
// ---------------------------------------------------------------------------
__global__ __launch_bounds__(256) void edge_pass2(const int* __restrict__ sidx,
                                                  const int* __restrict__ didx) {
    int r = blockIdx.y;
    int e = blockIdx.x * 8 + (threadIdx.x >> 5);
    if (e >= EE) return;
    int lane = threadIdx.x & 31;
    int s = __ldg(&sidx[r * EE + e]);
    int d = __ldg(&didx[r * EE + e]);
    float4 exv = g_ex[r * EE + e];
    float4 sv  = g_ssum[r * NN + d];
    int h = lane >> 3;
    float exh = (h == 0) ? exv.x : (h == 1) ? exv.y : (h == 2) ? exv.z : exv.w;
    float ssh = (h == 0) ? sv.x  : (h == 1) ? sv.y  : (h == 2) ? sv.z  : sv.w;
    float alpha = exh / (ssh + 1e-9f);
    float4 hv = *(const float4*)&g_hs[((size_t)r * NN + s) * 128 + lane * 4];
    red_add_v4((float4*)&g_rst[((size_t)r * NN + d) * 128 + lane * 4],
               make_float4(alpha * hv.x, alpha * hv.y, alpha * hv.z, alpha * hv.w));
}

// ---------------------------------------------------------------------------
// Kernel 7: z = elu(rst + bias_g) written in place; fused semantic-attention
//           logits: wsum[r] += sum_n tanh(z_n@W1 + b1)@W2
// ---------------------------------------------------------------------------
__global__ __launch_bounds__(256) void finalize_kernel(
        const float* __restrict__ bias_g, const float* __restrict__ W1,
        const float* __restrict__ b1, const float* __restrict__ W2) {
    int r = blockIdx.y;
    int row0 = blockIdx.x * 64;
    __shared__ float Ws[32][128];
    __shared__ float Zs[64][32];
    __shared__ float warp_sums[8];
    int tid = threadIdx.x;
    int lane = tid & 31;
    int wg = tid >> 5;
    float* rst = g_rst + (size_t)r * NN * 128;
    float acc[8][4] = {};
    for (int kk = 0; kk < 128; kk += 32) {
        for (int idx = tid; idx < 64 * 32; idx += 256) {
            int i = idx >> 5, k = idx & 31;
            int row = row0 + i;
            float z = 0.f;
            if (row < NN) {
                size_t off = (size_t)row * 128 + kk + k;
                float v = rst[off] + bias_g[r * 128 + kk + k];
                z = v > 0.f ? v : expm1f(v);
                rst[off] = z;                        // in-place: rst becomes z_r
            }
            Zs[i][k] = z;
        }
        for (int idx = tid; idx < 32 * 128; idx += 256) {
            int k = idx >> 7, g = idx & 127;
            Ws[k][g] = W1[(kk + k) * 128 + g];
        }
        __syncthreads();
        #pragma unroll
        for (int k = 0; k < 32; k++) {
            float4 w = *(const float4*)&Ws[k][lane * 4];
            #pragma unroll
            for (int i = 0; i < 8; i++) {
                float x = Zs[wg * 8 + i][k];
                acc[i][0] += x * w.x; acc[i][1] += x * w.y;
                acc[i][2] += x * w.z; acc[i][3] += x * w.w;
            }
        }
        __syncthreads();
    }
    float4 b1v = *(const float4*)&b1[lane * 4];
    float4 w2v = *(const float4*)&W2[lane * 4];
    float tot = 0.f;
    #pragma unroll
    for (int i = 0; i < 8; i++) {
        int row = row0 + wg * 8 + i;
        float t0 = tanhf(acc[i][0] + b1v.x);
        float t1 = tanhf(acc[i][1] + b1v.y);
        float t2 = tanhf(acc[i][2] + b1v.z);
        float t3 = tanhf(acc[i][3] + b1v.w);
        float p = t0 * w2v.x + t1 * w2v.y + t2 * w2v.z + t3 * w2v.w;
        #pragma unroll
        for (int off = 16; off; off >>= 1)
            p += __shfl_xor_sync(0xffffffffu, p, off);
        if (row < NN) tot += p;     // uniform across lanes
    }
    if (lane == 0) warp_sums[wg] = tot;
    __syncthreads();
    if (tid == 0) {
        float s = 0.f;
        #pragma unroll
        for (int i = 0; i < 8; i++) s += warp_sums[i];
        atomicAdd(&g_wsum[r], s);
    }
}

// ---------------------------------------------------------------------------
// Kernel 8: semantic softmax over relations; write att_mp tail of the output
// ---------------------------------------------------------------------------
__global__ void softmax_kernel(float* __restrict__ out) {
    if (threadIdx.x == 0) {
        float v[RR], m = -1e30f;
        for (int r = 0; r < RR; r++) { v[r] = g_wsum[r] / (float)NN; m = fmaxf(m, v[r]); }
        float s = 0.f;
        for (int r = 0; r < RR; r++) { v[r] = expf(v[r] - m); s += v[r]; }
        for (int r = 0; r < RR; r++) {
            float a = v[r] / s;
            g_a[r] = a;
            out[(size_t)NN * 128 + r] = a;
        }
    }
}

// ---------------------------------------------------------------------------
// Kernel 9: z = sum_r a[r] * z_r
// ---------------------------------------------------------------------------
__global__ void combine_kernel(float* __restrict__ out) {
    size_t stride = (size_t)gridDim.x * blockDim.x;
    size_t i = (size_t)blockIdx.x * blockDim.x + threadIdx.x;
    float a0 = g_a[0], a1 = g_a[1], a2 = g_a[2];
    const float4* r0 = (const float4*)g_rst;
    const float4* r1 = r0 + (size_t)NN * 32;
    const float4* r2 = r1 + (size_t)NN * 32;
    float4* o = (float4*)out;
    size_t n4 = (size_t)NN * 32;
    for (size_t j = i; j < n4; j += stride) {
        float4 x0 = r0[j], x1 = r1[j], x2 = r2[j];
        o[j] = make_float4(a0 * x0.x + a1 * x1.x + a2 * x2.x,
                           a0 * x0.y + a1 * x1.y + a2 * x2.y,
                           a0 * x0.z + a1 * x1.z + a2 * x2.z,
                           a0 * x0.w + a1 * x1.w + a2 * x2.w);
    }
}

// ---------------------------------------------------------------------------
// Launch
// ---------------------------------------------------------------------------
extern "C" void kernel_launch(void* const* d_in, const int* in_sizes, int n_in,
                              void* d_out, int out_size) {
    const float* dst_feat  = (const float*)d_in[0];
    const float* src_feats = (const float*)d_in[1];
    const int*   src_idx   = (const int*)  d_in[2];
    const int*   dst_idx   = (const int*)  d_in[3];
    const float* Wt_dst    = (const float*)d_in[4];
    const float* bt_dst    = (const float*)d_in[5];
    const float* Wt_src    = (const float*)d_in[6];
    const float* bt_src    = (const float*)d_in[7];
    const float* Wg        = (const float*)d_in[8];
    const float* attn_l    = (const float*)d_in[9];
    const float* attn_r    = (const float*)d_in[10];
    const float* bias_g    = (const float*)d_in[11];
    const float* W1        = (const float*)d_in[12];
    const float* b1        = (const float*)d_in[13];
    const float* W2        = (const float*)d_in[14];
    float* out = (float*)d_out;

    const int rowBlocks = (NN + 63) / 64;   // 1563

    init_kernel<<<2048, 256>>>();
    prep_wc_kernel<<<RR, 256>>>(Wt_src, Wg, bt_src);
    prep_v_kernel<<<RR, 128>>>(Wt_dst, bt_dst, Wg, attn_r);
    hs_gemm_kernel<<<dim3(rowBlocks, RR), 256>>>(src_feats, attn_l);
    er_kernel<<<(NN + 7) / 8, 256>>>(dst_feat);
    edge_pass1<<<dim3((EE + 255) / 256, RR), 256>>>(src_idx, dst_idx);
    edge_pass2<<<dim3((EE + 7) / 8, RR), 256>>>(src_idx, dst_idx);
    finalize_kernel<<<dim3(rowBlocks, RR), 256>>>(bias_g, W1, b1, W2);
    softmax_kernel<<<1, 32>>>(out);
    combine_kernel<<<2048, 256>>>(out);
}